// round 4
// baseline (speedup 1.0000x reference)
#include <cuda_runtime.h>
#include <cuda_bf16.h>
#include <math.h>

// Problem dims (fixed by dataset)
#define BB 64
#define SS 512
#define HH 768
#define LL 9

#define SPLIT 8            // threads per token
#define HC (HH / SPLIT)    // 96 features per chunk
#define F4C (HC / 4)       // 24 float4 per chunk
#define WREG (HC * 12 + 4) // region stride in floats (pad 4 -> bank rotation)

// Scratch (no device allocations allowed)
__device__ int g_cnt[BB];        // valid count per batch
__device__ int g_src[BB * SS];   // per-batch: src token index for dest d at [b*SS+d]

// ---------------------------------------------------------------------------
// Kernel 1: per-batch scan of valid_mask -> src map + counts, AND fill the
// whole output with softmax(bias) (tail slots; valid slots overwritten later).
// One block (512 threads) per batch row.
// ---------------------------------------------------------------------------
__global__ __launch_bounds__(512) void scan_fill_kernel(const int* __restrict__ mask,
                                                        const float* __restrict__ bias,
                                                        float* __restrict__ out) {
    int b = blockIdx.x;
    int s = threadIdx.x;
    int m = (mask[b * SS + s] == 1) ? 1 : 0;

    __shared__ int wsum[16];
    int lane = s & 31, wid = s >> 5;
    int v = m;
#pragma unroll
    for (int o = 1; o < 32; o <<= 1) {
        int t = __shfl_up_sync(0xffffffffu, v, o);
        if (lane >= o) v += t;
    }
    if (lane == 31) wsum[wid] = v;
    __syncthreads();
    if (wid == 0) {
        int x = (lane < 16) ? wsum[lane] : 0;
#pragma unroll
        for (int o = 1; o < 16; o <<= 1) {
            int t = __shfl_up_sync(0xffffffffu, x, o);
            if (lane >= o) x += t;
        }
        if (lane < 16) wsum[lane] = x;
    }
    __syncthreads();
    int incl = v + (wid ? wsum[wid - 1] : 0);
    if (m) g_src[b * SS + (incl - 1)] = s;
    if (s == SS - 1) g_cnt[b] = incl;

    // fill: softmax(bias) constant into every slot of this batch row
    float bv[LL];
#pragma unroll
    for (int l = 0; l < LL; l++) bv[l] = __ldg(bias + l);
    float mx = bv[0];
#pragma unroll
    for (int l = 1; l < LL; l++) mx = fmaxf(mx, bv[l]);
    float sum = 0.f;
#pragma unroll
    for (int l = 0; l < LL; l++) { bv[l] = __expf(bv[l] - mx); sum += bv[l]; }
    float r = 1.f / sum;
    float* op = out + (size_t)(b * SS + s) * LL;
#pragma unroll
    for (int l = 0; l < LL; l++) op[l] = bv[l] * r;
}

// ---------------------------------------------------------------------------
// Kernel 2: main compute. 8 threads per token (each covers 96 features),
// shfl reduction within the 8-lane group, softmax, write.
// W in shared: 8 per-chunk regions, each 96 rows x 12 floats + 4-float pad
// so the 8 chunks hit disjoint bank quartets (conflict-free, 4-way bcast).
// ---------------------------------------------------------------------------
#define NBLK 444

__global__ __launch_bounds__(256, 3) void main_kernel(const float* __restrict__ seq,
                                                      const float* __restrict__ W,
                                                      const float* __restrict__ bias,
                                                      float* __restrict__ out) {
    __shared__ float Ws[SPLIT * WREG];   // ~37 KB
    __shared__ float Bs[LL];
    __shared__ int s_cnt[BB];

    int tid = threadIdx.x;
    if (tid < LL) Bs[tid] = bias[tid];
    if (tid < BB) s_cnt[tid] = g_cnt[tid];
    for (int i = tid; i < SPLIT * WREG; i += 256) {
        int c = i / WREG, r = i % WREG;
        float val = 0.f;
        if (r < HC * 12) {
            int j = r / 12, col = r % 12;
            if (col < LL) val = W[(c * HC + j) * LL + col];
        }
        Ws[i] = val;
    }
    __syncthreads();

    int wid = tid >> 5, lane = tid & 31;
    int t_in = lane >> 3;      // token within group: 0..3
    int c    = lane & 7;       // chunk: 0..7
    int wbase = c * WREG;

    int warp_g = blockIdx.x * 8 + wid;
    int nwarps = NBLK * 8;

    // grid-stride over groups of 4 output slots
    for (int grp = warp_g; grp < (BB * SS) / 4; grp += nwarps) {
        int slot = grp * 4 + t_in;          // global dest slot
        int b = slot >> 9;
        int d = slot & (SS - 1);
        bool active = d < s_cnt[b];

        // fast skip: whole warp inactive
        if (__all_sync(0xffffffffu, !active)) continue;

        int s = active ? g_src[slot] : 0;   // inactive lanes read row 0 (harmless)

        const float4* xp = (const float4*)(seq + (size_t)(b * SS + s) * HH) + c * F4C;

        float acc[LL];
#pragma unroll
        for (int l = 0; l < LL; l++) acc[l] = 0.f;

        float4 A[4], Bf[4];

#define CONSUME(BUF, ST)                                                      \
        {                                                                     \
            _Pragma("unroll") for (int k = 0; k < 4; k++) {                   \
                int hl = (ST) * 16 + k * 4;                                   \
                float4 xv = BUF[k];                                           \
                float xs_[4] = {xv.x, xv.y, xv.z, xv.w};                      \
                _Pragma("unroll") for (int j = 0; j < 4; j++) {               \
                    const float4* wr = (const float4*)&Ws[wbase + (hl + j) * 12]; \
                    float4 w0 = wr[0];                                        \
                    float4 w1 = wr[1];                                        \
                    float w8 = Ws[wbase + (hl + j) * 12 + 8];                 \
                    float xs = xs_[j];                                        \
                    acc[0] = fmaf(xs, w0.x, acc[0]);                          \
                    acc[1] = fmaf(xs, w0.y, acc[1]);                          \
                    acc[2] = fmaf(xs, w0.z, acc[2]);                          \
                    acc[3] = fmaf(xs, w0.w, acc[3]);                          \
                    acc[4] = fmaf(xs, w1.x, acc[4]);                          \
                    acc[5] = fmaf(xs, w1.y, acc[5]);                          \
                    acc[6] = fmaf(xs, w1.z, acc[6]);                          \
                    acc[7] = fmaf(xs, w1.w, acc[7]);                          \
                    acc[8] = fmaf(xs, w8, acc[8]);                            \
                }                                                             \
            }                                                                 \
        }

        // 24 float4 = 6 stages of 4, double-buffered
#pragma unroll
        for (int k = 0; k < 4; k++) A[k] = xp[k];
#pragma unroll
        for (int st = 0; st < 6; st += 2) {
#pragma unroll
            for (int k = 0; k < 4; k++) Bf[k] = xp[(st + 1) * 4 + k];
            CONSUME(A, st);
            if (st + 2 < 6) {
#pragma unroll
                for (int k = 0; k < 4; k++) A[k] = xp[(st + 2) * 4 + k];
            }
            CONSUME(Bf, (st + 1));
        }
#undef CONSUME

        // reduce the 8 chunk-lanes of each token
#pragma unroll
        for (int o = 4; o >= 1; o >>= 1) {
#pragma unroll
            for (int l = 0; l < LL; l++)
                acc[l] += __shfl_xor_sync(0xffffffffu, acc[l], o);
        }

        if (active && c == 0) {
            float v[LL];
#pragma unroll
            for (int l = 0; l < LL; l++) v[l] = acc[l] + Bs[l];
            float m = v[0];
#pragma unroll
            for (int l = 1; l < LL; l++) m = fmaxf(m, v[l]);
            float sum = 0.f;
#pragma unroll
            for (int l = 0; l < LL; l++) { v[l] = __expf(v[l] - m); sum += v[l]; }
            float r = 1.f / sum;
            float* op = out + (size_t)slot * LL;
#pragma unroll
            for (int l = 0; l < LL; l++) op[l] = v[l] * r;
        }
    }
}

// ---------------------------------------------------------------------------
extern "C" void kernel_launch(void* const* d_in, const int* in_sizes, int n_in,
                              void* d_out, int out_size) {
    const float* seq  = (const float*)d_in[0];   // [64,512,768] f32
    const int*   mask = (const int*)d_in[1];     // [64,512] i32
    const float* W    = (const float*)d_in[2];   // [768,9] f32
    const float* bias = (const float*)d_in[3];   // [9] f32
    float* out = (float*)d_out;                  // [64,512,9] f32

    scan_fill_kernel<<<BB, SS>>>(mask, bias, out);
    main_kernel<<<NBLK, 256>>>(seq, W, bias, out);
}

// round 7
// speedup vs baseline: 1.5535x; 1.5535x over previous
#include <cuda_runtime.h>
#include <cuda_bf16.h>
#include <math.h>

// Problem dims (fixed by dataset)
#define BB 64
#define SS 512
#define HH 768
#define LL 9

#define SPLIT 4                 // chunks per token (lanes)
#define HC (HH / SPLIT)         // 192 features per chunk
#define F4C (HC / 4)            // 48 float4 per chunk
#define WREG (HC * 8 + 4)       // main W region stride (floats): 1540, mod32=4
#define W8REG (HC + 4)          // w8 quad region stride (floats): 196, mod32=4

// Scratch (no device allocations allowed)
__device__ int g_cnt[BB];        // valid count per batch
__device__ int g_src[BB * SS];   // per-batch: src token index for dest d
__device__ int g_items[BB * SS]; // global work list: b<<18 | d<<9 | s

// ---------------------------------------------------------------------------
// Kernel 1: per-batch scan of valid_mask -> src map + counts, AND fill the
// whole output with softmax(bias). One block (512 threads) per batch row.
// ---------------------------------------------------------------------------
__global__ __launch_bounds__(512) void scan_fill_kernel(const int* __restrict__ mask,
                                                        const float* __restrict__ bias,
                                                        float* __restrict__ out) {
    int b = blockIdx.x;
    int s = threadIdx.x;
    int m = (mask[b * SS + s] == 1) ? 1 : 0;

    __shared__ int wsum[16];
    int lane = s & 31, wid = s >> 5;
    int v = m;
#pragma unroll
    for (int o = 1; o < 32; o <<= 1) {
        int t = __shfl_up_sync(0xffffffffu, v, o);
        if (lane >= o) v += t;
    }
    if (lane == 31) wsum[wid] = v;
    __syncthreads();
    if (wid == 0) {
        int x = (lane < 16) ? wsum[lane] : 0;
#pragma unroll
        for (int o = 1; o < 16; o <<= 1) {
            int t = __shfl_up_sync(0xffffffffu, x, o);
            if (lane >= o) x += t;
        }
        if (lane < 16) wsum[lane] = x;
    }
    __syncthreads();
    int incl = v + (wid ? wsum[wid - 1] : 0);
    if (m) g_src[b * SS + (incl - 1)] = s;
    if (s == SS - 1) g_cnt[b] = incl;

    // fill: softmax(bias) constant into every slot of this batch row
    float bv[LL];
#pragma unroll
    for (int l = 0; l < LL; l++) bv[l] = __ldg(bias + l);
    float mx = bv[0];
#pragma unroll
    for (int l = 1; l < LL; l++) mx = fmaxf(mx, bv[l]);
    float sum = 0.f;
#pragma unroll
    for (int l = 0; l < LL; l++) { bv[l] = __expf(bv[l] - mx); sum += bv[l]; }
    float r = 1.f / sum;
    float* op = out + (size_t)(b * SS + s) * LL;
#pragma unroll
    for (int l = 0; l < LL; l++) op[l] = bv[l] * r;
}

// ---------------------------------------------------------------------------
// Kernel 2: build globally-compacted work list (perfect load balance)
// ---------------------------------------------------------------------------
__global__ __launch_bounds__(512) void build_kernel() {
    int b = blockIdx.x;
    int d = threadIdx.x;
    __shared__ int scnt[BB];
    __shared__ int soff;
    if (d < BB) scnt[d] = g_cnt[d];
    __syncthreads();
    if (d == 0) {
        int o = 0;
#pragma unroll
        for (int i = 0; i < BB; i++) o += (i < b) ? scnt[i] : 0;
        soff = o;
    }
    __syncthreads();
    if (d < scnt[b]) {
        g_items[soff + d] = (b << 18) | (d << 9) | g_src[b * SS + d];
    }
}

// ---------------------------------------------------------------------------
// Kernel 3: main compute. Warp = 16 work items: 8 token-lanes x 4 chunk-lanes,
// each lane handles TWO tokens that SHARE the W shared-memory loads
// (18 FMAs per W row-pair load -> fma-pipe-bound, LDS latency hidden by the
// two independent accumulator sets). w8 column packed in quads (1 LDS.128
// per 4 rows). Bank-rotated regions: conflict-free, 8-way broadcast.
// ---------------------------------------------------------------------------
#define NBLK 296

__global__ __launch_bounds__(256, 2) void main_kernel(const float* __restrict__ seq,
                                                      const float* __restrict__ W,
                                                      const float* __restrict__ bias,
                                                      float* __restrict__ out) {
    __shared__ float Ws[SPLIT * WREG];    // cols 0..7, 8 floats/row
    __shared__ float W8s[SPLIT * W8REG];  // col 8, packed 4 rows per float4
    __shared__ float Bs[LL];
    __shared__ int s_total;

    int tid = threadIdx.x;
    if (tid == 0) s_total = 0;
    if (tid < LL) Bs[tid] = bias[tid];
    for (int i = tid; i < SPLIT * WREG; i += 256) {
        int c = i / WREG, r = i % WREG;
        float val = 0.f;
        if (r < HC * 8) {
            int j = r / 8, col = r % 8;
            val = W[(c * HC + j) * LL + col];
        }
        Ws[i] = val;
    }
    for (int i = tid; i < SPLIT * W8REG; i += 256) {
        int c = i / W8REG, r = i % W8REG;
        float val = 0.f;
        if (r < HC) val = W[(c * HC + r) * LL + 8];
        W8s[i] = val;
    }
    __syncthreads();
    if (tid < BB) atomicAdd(&s_total, g_cnt[tid]);
    __syncthreads();

    int total = s_total;
    int n_sg = (total + 15) >> 4;   // supergroups of 16 work items

    int wid = tid >> 5, lane = tid & 31;
    int t_in = lane >> 2;   // token-lane 0..7
    int c    = lane & 3;    // chunk 0..3
    int wbase  = c * WREG;
    int w8base = c * W8REG;

    int warp_g = blockIdx.x * 8 + wid;
    int nwarps = NBLK * 8;

    for (int sg = warp_g; sg < n_sg; sg += nwarps) {
        int i1 = sg * 16 + t_in;
        int i2 = i1 + 8;
        bool a1 = i1 < total;
        bool a2 = i2 < total;
        int item1 = a1 ? g_items[i1] : 0;
        int item2 = a2 ? g_items[i2] : 0;
        int b1 = item1 >> 18, d1 = (item1 >> 9) & 511, s1 = item1 & 511;
        int b2 = item2 >> 18, d2 = (item2 >> 9) & 511, s2 = item2 & 511;

        const float4* xp1 = (const float4*)(seq + (size_t)(b1 * SS + s1) * HH) + c * F4C;
        const float4* xp2 = (const float4*)(seq + (size_t)(b2 * SS + s2) * HH) + c * F4C;

        float acc1[LL], acc2[LL];
#pragma unroll
        for (int l = 0; l < LL; l++) { acc1[l] = 0.f; acc2[l] = 0.f; }

        // stage = 2 float4 = 8 rows; 24 stages, double-buffered
        float4 A1[2], A2[2], B1[2], B2[2];

#define CONSUME(X1, X2, ST)                                                    \
        {                                                                      \
            _Pragma("unroll") for (int k = 0; k < 2; k++) {                    \
                int qg = (ST) * 2 + k;          /* quad-group index (4 rows) */\
                float4 w8q = *(const float4*)&W8s[w8base + qg * 4];            \
                float4 xv1 = X1[k];                                            \
                float4 xv2 = X2[k];                                            \
                float xs1_[4] = {xv1.x, xv1.y, xv1.z, xv1.w};                  \
                float xs2_[4] = {xv2.x, xv2.y, xv2.z, xv2.w};                  \
                float w8_[4] = {w8q.x, w8q.y, w8q.z, w8q.w};                   \
                _Pragma("unroll") for (int j = 0; j < 4; j++) {                \
                    int row = qg * 4 + j;                                      \
                    const float4* wr = (const float4*)&Ws[wbase + row * 8];    \
                    float4 w0 = wr[0];                                         \
                    float4 w1 = wr[1];                                         \
                    float xs1 = xs1_[j], xs2 = xs2_[j], w8 = w8_[j];           \
                    acc1[0] = fmaf(xs1, w0.x, acc1[0]);                        \
                    acc2[0] = fmaf(xs2, w0.x, acc2[0]);                        \
                    acc1[1] = fmaf(xs1, w0.y, acc1[1]);                        \
                    acc2[1] = fmaf(xs2, w0.y, acc2[1]);                        \
                    acc1[2] = fmaf(xs1, w0.z, acc1[2]);                        \
                    acc2[2] = fmaf(xs2, w0.z, acc2[2]);                        \
                    acc1[3] = fmaf(xs1, w0.w, acc1[3]);                        \
                    acc2[3] = fmaf(xs2, w0.w, acc2[3]);                        \
                    acc1[4] = fmaf(xs1, w1.x, acc1[4]);                        \
                    acc2[4] = fmaf(xs2, w1.x, acc2[4]);                        \
                    acc1[5] = fmaf(xs1, w1.y, acc1[5]);                        \
                    acc2[5] = fmaf(xs2, w1.y, acc2[5]);                        \
                    acc1[6] = fmaf(xs1, w1.z, acc1[6]);                        \
                    acc2[6] = fmaf(xs2, w1.z, acc2[6]);                        \
                    acc1[7] = fmaf(xs1, w1.w, acc1[7]);                        \
                    acc2[7] = fmaf(xs2, w1.w, acc2[7]);                        \
                    acc1[8] = fmaf(xs1, w8, acc1[8]);                          \
                    acc2[8] = fmaf(xs2, w8, acc2[8]);                          \
                }                                                              \
            }                                                                  \
        }

#pragma unroll
        for (int k = 0; k < 2; k++) { A1[k] = xp1[k]; A2[k] = xp2[k]; }
#pragma unroll
        for (int st = 0; st < 24; st += 2) {
#pragma unroll
            for (int k = 0; k < 2; k++) {
                B1[k] = xp1[(st + 1) * 2 + k];
                B2[k] = xp2[(st + 1) * 2 + k];
            }
            CONSUME(A1, A2, st);
            if (st + 2 < 24) {
#pragma unroll
                for (int k = 0; k < 2; k++) {
                    A1[k] = xp1[(st + 2) * 2 + k];
                    A2[k] = xp2[(st + 2) * 2 + k];
                }
            }
            CONSUME(B1, B2, st + 1);
        }
#undef CONSUME

        // reduce over the 4 chunk lanes (xor 1, 2); all lanes end with full sums
#pragma unroll
        for (int o = 1; o <= 2; o <<= 1) {
#pragma unroll
            for (int l = 0; l < LL; l++) {
                acc1[l] += __shfl_xor_sync(0xffffffffu, acc1[l], o);
                acc2[l] += __shfl_xor_sync(0xffffffffu, acc2[l], o);
            }
        }

        // lane c==0 finalizes token1, lane c==1 finalizes token2
        bool doit = (c == 0) ? a1 : ((c == 1) ? a2 : false);
        if (doit) {
            float v[LL];
            int slot;
            if (c == 0) {
#pragma unroll
                for (int l = 0; l < LL; l++) v[l] = acc1[l] + Bs[l];
                slot = b1 * SS + d1;
            } else {
#pragma unroll
                for (int l = 0; l < LL; l++) v[l] = acc2[l] + Bs[l];
                slot = b2 * SS + d2;
            }
            float m = v[0];
#pragma unroll
            for (int l = 1; l < LL; l++) m = fmaxf(m, v[l]);
            float sum = 0.f;
#pragma unroll
            for (int l = 0; l < LL; l++) { v[l] = __expf(v[l] - m); sum += v[l]; }
            float r = 1.f / sum;
            float* op = out + (size_t)slot * LL;
#pragma unroll
            for (int l = 0; l < LL; l++) op[l] = v[l] * r;
        }
    }
}

// ---------------------------------------------------------------------------
extern "C" void kernel_launch(void* const* d_in, const int* in_sizes, int n_in,
                              void* d_out, int out_size) {
    const float* seq  = (const float*)d_in[0];   // [64,512,768] f32
    const int*   mask = (const int*)d_in[1];     // [64,512] i32
    const float* W    = (const float*)d_in[2];   // [768,9] f32
    const float* bias = (const float*)d_in[3];   // [9] f32
    float* out = (float*)d_out;                  // [64,512,9] f32

    scan_fill_kernel<<<BB, SS>>>(mask, bias, out);
    build_kernel<<<BB, SS>>>();
    main_kernel<<<NBLK, 256>>>(seq, W, bias, out);
}